// round 6
// baseline (speedup 1.0000x reference)
#include <cuda_runtime.h>
#include <cuda_bf16.h>
#include <mma.h>
#include <cstdint>
#include <cstddef>

using namespace nvcuda;

#define BB 16
#define CCH 256
#define HH 56
#define WW 56
#define XT_H 58
#define XT_W 66

#define XS_LD 264                         // padded channel stride (elements)
#define XS_ELEMS (4 * 66 * XS_LD)         // 69696 bf16
#define XS_BYTES (XS_ELEMS * 2)           // 139392 B
#define WSTE (64 * 136)                   // weight stage elements (64 c x 136 o-pitch)
#define WST_BYTES (WSTE * 2)              // 17408 B
#define SCR_OFF (XS_BYTES + 2 * WST_BYTES)          // 174208
#define SMEM_TOTAL (SCR_OFF + 8 * 16 * 17 * 4)      // 182912 B

#define N_ITEMS 896                       // 448 M-tiles x 2 N-halves
#define N_CTAS 148

// ---------------- device-global scratch (allocation-free) ----------------
__device__ __nv_bfloat16 g_xt[BB * XT_H * XT_W * CCH];   // padded channels-last x (~31 MB)
__device__ __nv_bfloat16 g_wt[9 * CCH * CCH];            // conv0 weights [tap][c][o]
__device__ float g_fsum[BB * CCH];                       // spatial sums of relu(conv)
__device__ float g_c1t[CCH * CCH];                       // center taps, [c][o]
__device__ float g_c2t[CCH * CCH];
__device__ float g_c3t[CCH * CCH];
__device__ float g_c4t[CCH * CCH];
__device__ float g_fc1t[CCH * CCH];
__device__ float g_w1t[CCH * 64];
__device__ float g_w2c[64];

// ---------------- cp.async helpers ----------------
__device__ __forceinline__ void cp16(void* dst_smem, const void* src_gmem) {
    unsigned int d = (unsigned int)__cvta_generic_to_shared(dst_smem);
    asm volatile("cp.async.cg.shared.global [%0], [%1], 16;\n" :: "r"(d), "l"(src_gmem) : "memory");
}
__device__ __forceinline__ void cp_commit() { asm volatile("cp.async.commit_group;\n" ::: "memory"); }
__device__ __forceinline__ void cp_wait0()  { asm volatile("cp.async.wait_group 0;\n" ::: "memory"); }

// ---------------- pre-pass kernels ----------------
// zero only the halo of g_xt, plus g_fsum
__global__ void k_zero_halo() {
    int gid = blockIdx.x * 256 + threadIdx.x;
    if (gid < BB * CCH) g_fsum[gid] = 0.f;
    int n = 16 * 692 * 32;                 // 692 halo positions per batch, 32 uint4 chunks each
    if (gid >= n) return;
    int k8 = gid & 31;
    int p  = (gid >> 5) % 692;
    int b  = gid / (692 * 32);
    int row, col;
    if (p < 66)       { row = 0;  col = p; }
    else if (p < 132) { row = 57; col = p - 66; }
    else {
        int q = p - 132;
        row = 1 + q / 10;
        int c10 = q % 10;
        col = (c10 == 0) ? 0 : (56 + c10);
    }
    ((uint4*)g_xt)[(((size_t)b * XT_H + row) * XT_W + col) * 32 + k8] = make_uint4(0, 0, 0, 0);
}

// conv0 weights [o][c][3][3] fp32 -> [tap][c][o] bf16  (9-way ILP, coalesced writes)
__global__ void k_wt(const float* __restrict__ w0) {
    int idx = blockIdx.x * 256 + threadIdx.x;     // 65536
    int o = idx & 255, c = idx >> 8;
    const float* src = w0 + ((size_t)o * 256 + c) * 9;
    float v[9];
#pragma unroll
    for (int t = 0; t < 9; t++) v[t] = src[t];
#pragma unroll
    for (int t = 0; t < 9; t++)
        g_wt[(size_t)t * 65536 + c * 256 + o] = __float2bfloat16(v[t]);
}

// NCHW fp32 -> padded [b][h+1][w+1][c] bf16 (32x32 smem transpose tiles)
__global__ void k_tr(const float* __restrict__ x) {
    __shared__ float tile[32][33];
    int wt = blockIdx.x;                // 0..1
    int h  = blockIdx.y;                // 0..55
    int z  = blockIdx.z;                // b*8 + cblock
    int b = z >> 3, ct = z & 7;
    int tx = threadIdx.x, ty = threadIdx.y;
    int c0 = ct * 32, w0 = wt * 32;
#pragma unroll
    for (int i = 0; i < 4; i++) {
        int c = c0 + ty + i * 8, w = w0 + tx;
        if (w < WW) tile[ty + i * 8][tx] = x[(((size_t)b * CCH + c) * HH + h) * WW + w];
    }
    __syncthreads();
#pragma unroll
    for (int i = 0; i < 4; i++) {
        int w = w0 + ty + i * 8, c = c0 + tx;
        if (w < WW)
            g_xt[(((size_t)b * XT_H + h + 1) * XT_W + (w + 1)) * CCH + c] =
                __float2bfloat16(tile[tx][ty + i * 8]);
    }
}

// center taps + fc1, transposed to [c][o]
__global__ void k_cent(const float* __restrict__ w01, const float* __restrict__ w02,
                       const float* __restrict__ w03, const float* __restrict__ w04,
                       const float* __restrict__ fc1, const float* __restrict__ w1,
                       const float* __restrict__ w2) {
    int idx = blockIdx.x * 256 + threadIdx.x;   // < 65536
    int o = idx & 255, c = idx >> 8;
    g_c1t[c * 256 + o]  = w01[(o * 256 + c) * 9 + 4];
    g_c2t[c * 256 + o]  = w02[(o * 256 + c) * 9 + 4];
    g_c3t[c * 256 + o]  = w03[(o * 256 + c) * 9 + 4];
    g_c4t[c * 256 + o]  = w04[(o * 256 + c) * 9 + 4];
    g_fc1t[c * 256 + o] = fc1[o * 256 + c];
    if (o < 64) g_w1t[c * 64 + o] = w1[(o * 256 + c) * 9 + 4];
    if (idx < 64) g_w2c[idx] = w2[idx * 9 + 4];
}

// ---------------- fused conv3x3 + bias + relu + spatial-sum (bf16 WMMA, persistent) ----
__global__ void __launch_bounds__(256, 1) k_conv(const float* __restrict__ bias0) {
    extern __shared__ __align__(16) unsigned char sraw[];
    __nv_bfloat16* xs  = (__nv_bfloat16*)sraw;               // [4][66][264]
    __nv_bfloat16* wsm = (__nv_bfloat16*)(sraw + XS_BYTES);  // 2 x [64][136]
    float* scrbase     = (float*)(sraw + SCR_OFF);           // 8 x [16][17]

    int tid = threadIdx.x, wid = tid >> 5, lane = tid & 31;
    int warpM = wid & 1, warpN = wid >> 1;    // 2M x 4N
    int rowl = warpM;                          // local image row 0/1
    int n0w  = warpN * 32;                     // col offset within 128-half
    float* scr = scrbase + wid * (16 * 17);

    int cta = blockIdx.x;
    int lo = (int)((long)cta * N_ITEMS / N_CTAS);
    int hi = (int)((long)(cta + 1) * N_ITEMS / N_CTAS);
    int cur_mtile = -1;

    for (int item = lo; item < hi; item++) {
        int mtile = item >> 1, nh = item & 1;
        int b = mtile / 28, h0 = (mtile % 28) * 2;
        int n0h = nh * 128;

        if (mtile != cur_mtile) {
            cur_mtile = mtile;
            // stage x tile: xt rows h0..h0+3, cols 0..65, 256 ch (pitch 264)
            for (int i = tid; i < 4 * 66 * 32; i += 256) {
                int k8 = i & 31;
                int col = (i >> 5) % 66;
                int r = i / (66 * 32);
                cp16(xs + ((r * 66 + col) * XS_LD + k8 * 8),
                     g_xt + ((((size_t)b * XT_H + h0 + r) * XT_W + col) * CCH + k8 * 8));
            }
            cp_commit();
        }

        // weight stage 0 (tap 0, c0 0)
        {
            const __nv_bfloat16* src = g_wt + n0h;
            for (int i = tid; i < 64 * 16; i += 256) {
                int o8 = i & 15, row = i >> 4;
                cp16(wsm + row * 136 + o8 * 8, src + (size_t)row * 256 + o8 * 8);
            }
            cp_commit();
        }
        cp_wait0();
        __syncthreads();

        wmma::fragment<wmma::accumulator, 16, 16, 16, float> acc[4][2];
#pragma unroll
        for (int mi = 0; mi < 4; mi++)
#pragma unroll
            for (int nf = 0; nf < 2; nf++) wmma::fill_fragment(acc[mi][nf], 0.f);

        for (int s = 0; s < 36; s++) {
            int buf = s & 1;
            if (s + 1 < 36) {                 // prefetch next weight stage
                int s2 = s + 1;
                int tap2 = s2 >> 2, c02 = (s2 & 3) << 6;
                const __nv_bfloat16* src = g_wt + (size_t)tap2 * 65536 + (size_t)c02 * 256 + n0h;
                __nv_bfloat16* dst = wsm + (buf ^ 1) * WSTE;
                for (int i = tid; i < 64 * 16; i += 256) {
                    int o8 = i & 15, row = i >> 4;
                    cp16(dst + row * 136 + o8 * 8, src + (size_t)row * 256 + o8 * 8);
                }
                cp_commit();
            }

            int tap = s >> 2;
            int kh = tap / 3, kw = tap - kh * 3;
            int cbase = (s & 3) << 6;
            const __nv_bfloat16* arow  = xs + ((rowl + kh) * 66 + kw) * XS_LD + cbase;
            const __nv_bfloat16* bbase = wsm + buf * WSTE + n0w;

#pragma unroll
            for (int k16 = 0; k16 < 4; k16++) {
                wmma::fragment<wmma::matrix_a, 16, 16, 16, __nv_bfloat16, wmma::row_major> a[4];
#pragma unroll
                for (int mi = 0; mi < 4; mi++)
                    wmma::load_matrix_sync(a[mi], arow + mi * 16 * XS_LD + k16 * 16, XS_LD);
#pragma unroll
                for (int nf = 0; nf < 2; nf++) {
                    wmma::fragment<wmma::matrix_b, 16, 16, 16, __nv_bfloat16, wmma::row_major> bf;
                    wmma::load_matrix_sync(bf, bbase + (k16 * 16) * 136 + nf * 16, 136);
#pragma unroll
                    for (int mi = 0; mi < 4; mi++)
                        wmma::mma_sync(acc[mi][nf], a[mi], bf, acc[mi][nf]);
                }
            }

            cp_wait0();
            __syncthreads();
        }

        // epilogue: per-warp fragment dump -> bias+relu -> column sums -> atomics
#pragma unroll
        for (int nf = 0; nf < 2; nf++) {
            int o = n0h + n0w + nf * 16 + (lane & 15);
            float bo = bias0[o];
            float colsum = 0.f;
#pragma unroll
            for (int mi = 0; mi < 4; mi++) {
                wmma::store_matrix_sync(scr, acc[mi][nf], 17, wmma::mem_row_major);
                __syncwarp();
                if (lane < 16) {
                    int rmax = (mi == 3) ? 8 : 16;      // cols >= 56 invalid
                    for (int r = 0; r < rmax; r++)
                        colsum += fmaxf(scr[r * 17 + (lane & 15)] + bo, 0.f);
                }
                __syncwarp();
            }
            if (lane < 16) atomicAdd(&g_fsum[b * 256 + o], colsum);
        }
    }
}

// ---------------- tail: all 1x1-spatial ops + CRF, one block per batch ----------------
__global__ void k_tail(const float* __restrict__ b0_1, const float* __restrict__ b0_2,
                       const float* __restrict__ b0_3, const float* __restrict__ b0_4,
                       const float* __restrict__ b1,   const float* __restrict__ b2,
                       const float* __restrict__ fc2w, const float* __restrict__ fc2b,
                       const float* __restrict__ compat, const float* __restrict__ sw,
                       float* __restrict__ out) {
    __shared__ float s_a[256], s_b[256], s_f3s[64], s_vs, s_red[256];
    int b = blockIdx.x, t = threadIdx.x;

    s_a[t] = g_fsum[b * 256 + t] * (1.f / 3136.f);   // f1c
    __syncthreads();

    float a2 = 0.f, avc = 0.f;
    for (int c = 0; c < 256; c++) {
        float v = s_a[c];
        a2  += g_c1t[c * 256 + t] * v;
        avc += g_fc1t[c * 256 + t] * v;
    }
    float f2 = fmaxf(a2 + b0_1[t], 0.f);
    float vc = 1.f / (1.f + expf(-avc));
    s_b[t] = vc * f2;                                 // f_c
    __syncthreads();

    float a3 = 0.f;
    for (int c = 0; c < 256; c++) a3 += g_c2t[c * 256 + t] * s_b[c];
    float f3 = fmaxf(a3 + b0_2[t], 0.f);
    __syncthreads();
    s_a[t] = f3;
    __syncthreads();

    float a4 = 0.f;
    for (int c = 0; c < 256; c++) a4 += g_c3t[c * 256 + t] * s_a[c];
    float f4 = fmaxf(a4 + b0_3[t], 0.f);
    if (t < 64) {
        float as = 0.f;
        for (int c = 0; c < 256; c++) as += g_w1t[c * 64 + t] * s_a[c];
        s_f3s[t] = fmaxf(as + b1[t], 0.f);
    }
    __syncthreads();

    if (t == 0) {
        float u = 0.f;
        for (int c = 0; c < 64; c++) u += g_w2c[c] * s_f3s[c];
        u = fmaxf(u + b2[0], 0.f);
        float c00 = compat[0], c01 = compat[1], c10 = compat[2], c11 = compat[3];
        float sw0 = sw[0], sw1 = sw[1];
        float m = fabsf(u);
        float e0 = expf(u - m), e1 = expf(-u - m);
        float q0 = e0 / (e0 + e1), q1 = e1 / (e0 + e1);
        for (int it = 0; it < 5; it++) {
            float m0 = 0.25f * q0 * sw0, m1 = 0.25f * q1 * sw1;
            float p0 = c00 * m0 + c01 * m1;
            float p1 = c10 * m0 + c11 * m1;
            float x0 = u - p0, x1 = -u - p1;
            float mm = fmaxf(x0, x1);
            float f0 = expf(x0 - mm), f1 = expf(x1 - mm);
            float ssum = f0 + f1;
            q0 = f0 / ssum; q1 = f1 / ssum;
        }
        s_vs = q1;
    }
    __syncthreads();

    s_b[t] = s_vs * f4;
    __syncthreads();
    float ar = 0.f;
    for (int c = 0; c < 256; c++) ar += g_c4t[c * 256 + t] * s_b[c];
    float fr = fmaxf(ar + b0_4[t], 0.f);

    s_red[t] = fc2w[t] * fr;
    __syncthreads();
    for (int s = 128; s > 0; s >>= 1) {
        if (t < s) s_red[t] += s_red[t + s];
        __syncthreads();
    }
    if (t == 0) out[b] = 1.f / (1.f + expf(-(s_red[0] + fc2b[0])));
}

// ---------------- launch ----------------
extern "C" void kernel_launch(void* const* d_in, const int* in_sizes, int n_in,
                              void* d_out, int out_size) {
    const float* x     = (const float*)d_in[0];
    const float* w0_0  = (const float*)d_in[1];
    const float* b0_0  = (const float*)d_in[2];
    const float* w0_1  = (const float*)d_in[3];
    const float* b0_1  = (const float*)d_in[4];
    const float* w0_2  = (const float*)d_in[5];
    const float* b0_2  = (const float*)d_in[6];
    const float* w0_3  = (const float*)d_in[7];
    const float* b0_3  = (const float*)d_in[8];
    const float* w0_4  = (const float*)d_in[9];
    const float* b0_4  = (const float*)d_in[10];
    const float* w1    = (const float*)d_in[11];
    const float* b1    = (const float*)d_in[12];
    const float* w2    = (const float*)d_in[13];
    const float* b2    = (const float*)d_in[14];
    const float* fc1w  = (const float*)d_in[15];
    const float* fc2w  = (const float*)d_in[16];
    const float* fc2b  = (const float*)d_in[17];
    const float* compat= (const float*)d_in[18];
    const float* sw    = (const float*)d_in[19];
    float* out = (float*)d_out;

    cudaFuncSetAttribute(k_conv, cudaFuncAttributeMaxDynamicSharedMemorySize, SMEM_TOTAL);

    k_zero_halo<<<1384, 256>>>();
    k_wt<<<256, 256>>>(w0_0);
    k_tr<<<dim3(2, 56, 128), dim3(32, 8)>>>(x);
    k_conv<<<N_CTAS, 256, SMEM_TOTAL>>>(b0_0);
    k_cent<<<256, 256>>>(w0_1, w0_2, w0_3, w0_4, fc1w, w1, w2);
    k_tail<<<16, 256>>>(b0_1, b0_2, b0_3, b0_4, b1, b2, fc2w, fc2b, compat, sw, out);
}

// round 8
// speedup vs baseline: 2.0165x; 2.0165x over previous
#include <cuda_runtime.h>
#include <cuda_fp16.h>
#include <mma.h>
#include <cstdint>
#include <cstddef>

using namespace nvcuda;

#define BB 16
#define CCH 256
#define HH 56
#define WW 56
#define XT_H 58
#define XT_W 66

#define AST 72                            // stage pitch (half elements)
#define A_STAGE (128 * AST)               // one A stage (half)
#define B_STAGE (256 * AST)               // one B stage (half)
#define SMEM_TOTAL ((2 * A_STAGE + 2 * B_STAGE) * 2)   // 110592 B

#define N_ITEMS 448                       // 16 batches * 28 two-row strips (M=128, N=256)
#define N_CTAS 296                        // 2 CTAs/SM persistent

// ---------------- device-global scratch (allocation-free) ----------------
__device__ __half g_xt[BB * XT_H * XT_W * CCH];    // padded channels-last x, fp16 (~31 MB)
__device__ __half g_wt2[9 * CCH * CCH];            // conv0 weights [tap][o][c] fp16
__device__ float g_fsum[BB * CCH];                 // spatial sums of relu(conv)
__device__ float g_c1t[CCH * CCH];                 // center taps, [c][o]
__device__ float g_c2t[CCH * CCH];
__device__ float g_c3t[CCH * CCH];
__device__ float g_c4t[CCH * CCH];
__device__ float g_fc1t[CCH * CCH];
__device__ float g_w1t[CCH * 64];
__device__ float g_w2c[64];

// ---------------- cp.async helpers ----------------
__device__ __forceinline__ void cp16(void* dst_smem, const void* src_gmem) {
    unsigned int d = (unsigned int)__cvta_generic_to_shared(dst_smem);
    asm volatile("cp.async.cg.shared.global [%0], [%1], 16;\n" :: "r"(d), "l"(src_gmem) : "memory");
}
__device__ __forceinline__ void cp_commit() { asm volatile("cp.async.commit_group;\n" ::: "memory"); }
__device__ __forceinline__ void cp_wait0()  { asm volatile("cp.async.wait_group 0;\n" ::: "memory"); }
__device__ __forceinline__ void cp_wait1()  { asm volatile("cp.async.wait_group 1;\n" ::: "memory"); }

// ---------------- pre-pass kernels ----------------
// zero only the halo of g_xt, plus g_fsum
__global__ void k_zero_halo() {
    int gid = blockIdx.x * 256 + threadIdx.x;
    if (gid < BB * CCH) g_fsum[gid] = 0.f;
    int n = 16 * 692 * 32;
    if (gid >= n) return;
    int k8 = gid & 31;
    int p  = (gid >> 5) % 692;
    int b  = gid / (692 * 32);
    int row, col;
    if (p < 66)       { row = 0;  col = p; }
    else if (p < 132) { row = 57; col = p - 66; }
    else {
        int q = p - 132;
        row = 1 + q / 10;
        int c10 = q % 10;
        col = (c10 == 0) ? 0 : (56 + c10);
    }
    ((uint4*)g_xt)[(((size_t)b * XT_H + row) * XT_W + col) * 32 + k8] = make_uint4(0, 0, 0, 0);
}

// conv0 weights [o][c][3][3] fp32 -> [tap][o][c] fp16
__global__ void k_wt(const float* __restrict__ w0) {
    int idx = blockIdx.x * 256 + threadIdx.x;     // 65536
    int c = idx & 255, o = idx >> 8;
    const float* src = w0 + ((size_t)o * 256 + c) * 9;
    float v[9];
#pragma unroll
    for (int t = 0; t < 9; t++) v[t] = src[t];
#pragma unroll
    for (int t = 0; t < 9; t++)
        g_wt2[((size_t)t * 256 + o) * 256 + c] = __float2half(v[t]);
}

// NCHW fp32 -> padded [b][h+1][w+1][c] fp16 (32x32 smem transpose tiles)
__global__ void k_tr(const float* __restrict__ x) {
    __shared__ float tile[32][33];
    int wt = blockIdx.x;                // 0..1
    int h  = blockIdx.y;                // 0..55
    int z  = blockIdx.z;                // b*8 + cblock
    int b = z >> 3, ct = z & 7;
    int tx = threadIdx.x, ty = threadIdx.y;
    int c0 = ct * 32, w0 = wt * 32;
#pragma unroll
    for (int i = 0; i < 4; i++) {
        int c = c0 + ty + i * 8, w = w0 + tx;
        if (w < WW) tile[ty + i * 8][tx] = x[(((size_t)b * CCH + c) * HH + h) * WW + w];
    }
    __syncthreads();
#pragma unroll
    for (int i = 0; i < 4; i++) {
        int w = w0 + ty + i * 8, c = c0 + tx;
        if (w < WW)
            g_xt[(((size_t)b * XT_H + h + 1) * XT_W + (w + 1)) * CCH + c] =
                __float2half(tile[tx][ty + i * 8]);
    }
}

// center taps + fc1, transposed to [c][o]
__global__ void k_cent(const float* __restrict__ w01, const float* __restrict__ w02,
                       const float* __restrict__ w03, const float* __restrict__ w04,
                       const float* __restrict__ fc1, const float* __restrict__ w1,
                       const float* __restrict__ w2) {
    int idx = blockIdx.x * 256 + threadIdx.x;   // < 65536
    int o = idx & 255, c = idx >> 8;
    g_c1t[c * 256 + o]  = w01[(o * 256 + c) * 9 + 4];
    g_c2t[c * 256 + o]  = w02[(o * 256 + c) * 9 + 4];
    g_c3t[c * 256 + o]  = w03[(o * 256 + c) * 9 + 4];
    g_c4t[c * 256 + o]  = w04[(o * 256 + c) * 9 + 4];
    g_fc1t[c * 256 + o] = fc1[o * 256 + c];
    if (o < 64) g_w1t[c * 64 + o] = w1[(o * 256 + c) * 9 + 4];
    if (idx < 64) g_w2c[idx] = w2[idx * 9 + 4];
}

// ---------------- stage loader: A [128m x 64k], B [256o x 64k], shift in addressing ----
__device__ __forceinline__ void stage_load(int tid, __half* Adst, __half* Bdst,
                                           int b, int h0, int tap, int cc) {
    int kh = tap / 3, kw = tap - kh * 3;
    const __half* xbase = g_xt + (((size_t)b * XT_H + h0 + kh) * XT_W + kw) * CCH + cc * 64;
    for (int i = tid; i < 1024; i += 256) {
        int c8 = i & 7, m = i >> 3;
        int r = m >> 6, col = m & 63;
        cp16(Adst + m * AST + c8 * 8, xbase + ((size_t)r * XT_W + col) * CCH + c8 * 8);
    }
    const __half* wbase = g_wt2 + (size_t)tap * 65536 + cc * 64;
    for (int i = tid; i < 2048; i += 256) {
        int c8 = i & 7, o = i >> 3;
        cp16(Bdst + o * AST + c8 * 8, wbase + (size_t)o * 256 + c8 * 8);
    }
}

// ---------------- fused conv3x3 + bias + relu + spatial-sum (fp16 WMMA, 2 CTA/SM) -----
__global__ void __launch_bounds__(256, 2) k_conv(const float* __restrict__ bias0) {
    extern __shared__ __align__(128) __half sm[];
    __half* A0 = sm;                     // 2 x [128][72]
    __half* B0 = sm + 2 * A_STAGE;       // 2 x [256][72]

    int tid = threadIdx.x, wid = tid >> 5, lane = tid & 31;
    int warpM = wid >> 2, warpN = wid & 3;        // 2M x 4N
    int m0 = warpM * 64, n0 = warpN * 64;

    int cta = blockIdx.x;
    int lo = (int)((long)cta * N_ITEMS / N_CTAS);
    int hi = (int)((long)(cta + 1) * N_ITEMS / N_CTAS);

    for (int item = lo; item < hi; item++) {
        int b = item / 28, h0 = (item % 28) * 2;

        stage_load(tid, A0, B0, b, h0, 0, 0);
        cp_commit();

        wmma::fragment<wmma::accumulator, 16, 16, 16, __half> acc[4][4];
#pragma unroll
        for (int mi = 0; mi < 4; mi++)
#pragma unroll
            for (int nf = 0; nf < 4; nf++) wmma::fill_fragment(acc[mi][nf], __float2half(0.f));

        for (int s = 0; s < 36; s++) {
            __half* As = A0 + (s & 1) * A_STAGE;
            __half* Bs = B0 + (s & 1) * B_STAGE;
            if (s + 1 < 36) {
                int s2 = s + 1;
                stage_load(tid, A0 + (s2 & 1) * A_STAGE, B0 + (s2 & 1) * B_STAGE,
                           b, h0, s2 % 9, s2 / 9);
                cp_commit();
                cp_wait1();
            } else {
                cp_wait0();
            }
            __syncthreads();

#pragma unroll
            for (int k16 = 0; k16 < 4; k16++) {
                wmma::fragment<wmma::matrix_a, 16, 16, 16, __half, wmma::row_major> a[4];
#pragma unroll
                for (int mi = 0; mi < 4; mi++)
                    wmma::load_matrix_sync(a[mi], As + (m0 + mi * 16) * AST + k16 * 16, AST);
#pragma unroll
                for (int nf = 0; nf < 4; nf++) {
                    wmma::fragment<wmma::matrix_b, 16, 16, 16, __half, wmma::col_major> bfr;
                    wmma::load_matrix_sync(bfr, Bs + (n0 + nf * 16) * AST + k16 * 16, AST);
#pragma unroll
                    for (int mi = 0; mi < 4; mi++)
                        wmma::mma_sync(acc[mi][nf], a[mi], bfr, acc[mi][nf]);
                }
            }
            __syncthreads();
        }

        // epilogue: per-warp fragment dump (reuse A region) -> bias+relu -> col sums
        __half* scr = sm + wid * (16 * 24);
        int ocol = lane & 15;
#pragma unroll
        for (int nf = 0; nf < 4; nf++) {
            int o = n0 + nf * 16 + ocol;
            float bo = bias0[o];
            float csum = 0.f;
#pragma unroll
            for (int mi = 0; mi < 4; mi++) {
                wmma::store_matrix_sync(scr, acc[mi][nf], 24, wmma::mem_row_major);
                __syncwarp();
                if (lane < 16) {
                    int rmax = (mi == 3) ? 8 : 16;      // within-64 col = mi*16+r; valid < 56
                    for (int r = 0; r < rmax; r++)
                        csum += fmaxf(__half2float(scr[r * 24 + ocol]) + bo, 0.f);
                }
                __syncwarp();
            }
            if (lane < 16) atomicAdd(&g_fsum[b * 256 + o], csum);
        }
        __syncthreads();     // scratch (A region) free before next item's stage 0
    }
}

// ---------------- tail: all 1x1-spatial ops + CRF, one block per batch ----------------
__global__ void k_tail(const float* __restrict__ b0_1, const float* __restrict__ b0_2,
                       const float* __restrict__ b0_3, const float* __restrict__ b0_4,
                       const float* __restrict__ b1,   const float* __restrict__ b2,
                       const float* __restrict__ fc2w, const float* __restrict__ fc2b,
                       const float* __restrict__ compat, const float* __restrict__ sw,
                       float* __restrict__ out) {
    __shared__ float s_a[256], s_b[256], s_f3s[64], s_vs, s_red[256];
    int b = blockIdx.x, t = threadIdx.x;

    s_a[t] = g_fsum[b * 256 + t] * (1.f / 3136.f);   // f1c
    __syncthreads();

    float a2 = 0.f, avc = 0.f;
    for (int c = 0; c < 256; c++) {
        float v = s_a[c];
        a2  += g_c1t[c * 256 + t] * v;
        avc += g_fc1t[c * 256 + t] * v;
    }
    float f2 = fmaxf(a2 + b0_1[t], 0.f);
    float vc = 1.f / (1.f + expf(-avc));
    s_b[t] = vc * f2;                                 // f_c
    __syncthreads();

    float a3 = 0.f;
    for (int c = 0; c < 256; c++) a3 += g_c2t[c * 256 + t] * s_b[c];
    float f3 = fmaxf(a3 + b0_2[t], 0.f);
    __syncthreads();
    s_a[t] = f3;
    __syncthreads();

    float a4 = 0.f;
    for (int c = 0; c < 256; c++) a4 += g_c3t[c * 256 + t] * s_a[c];
    float f4 = fmaxf(a4 + b0_3[t], 0.f);
    if (t < 64) {
        float as = 0.f;
        for (int c = 0; c < 256; c++) as += g_w1t[c * 64 + t] * s_a[c];
        s_f3s[t] = fmaxf(as + b1[t], 0.f);
    }
    __syncthreads();

    if (t == 0) {
        float u = 0.f;
        for (int c = 0; c < 64; c++) u += g_w2c[c] * s_f3s[c];
        u = fmaxf(u + b2[0], 0.f);
        float c00 = compat[0], c01 = compat[1], c10 = compat[2], c11 = compat[3];
        float sw0 = sw[0], sw1 = sw[1];
        float m = fabsf(u);
        float e0 = expf(u - m), e1 = expf(-u - m);
        float q0 = e0 / (e0 + e1), q1 = e1 / (e0 + e1);
        for (int it = 0; it < 5; it++) {
            float m0 = 0.25f * q0 * sw0, m1 = 0.25f * q1 * sw1;
            float p0 = c00 * m0 + c01 * m1;
            float p1 = c10 * m0 + c11 * m1;
            float x0 = u - p0, x1 = -u - p1;
            float mm = fmaxf(x0, x1);
            float f0 = expf(x0 - mm), f1 = expf(x1 - mm);
            float ssum = f0 + f1;
            q0 = f0 / ssum; q1 = f1 / ssum;
        }
        s_vs = q1;
    }
    __syncthreads();

    s_b[t] = s_vs * f4;
    __syncthreads();
    float ar = 0.f;
    for (int c = 0; c < 256; c++) ar += g_c4t[c * 256 + t] * s_b[c];
    float fr = fmaxf(ar + b0_4[t], 0.f);

    s_red[t] = fc2w[t] * fr;
    __syncthreads();
    for (int s = 128; s > 0; s >>= 1) {
        if (t < s) s_red[t] += s_red[t + s];
        __syncthreads();
    }
    if (t == 0) out[b] = 1.f / (1.f + expf(-(s_red[0] + fc2b[0])));
}

// ---------------- launch ----------------
extern "C" void kernel_launch(void* const* d_in, const int* in_sizes, int n_in,
                              void* d_out, int out_size) {
    const float* x     = (const float*)d_in[0];
    const float* w0_0  = (const float*)d_in[1];
    const float* b0_0  = (const float*)d_in[2];
    const float* w0_1  = (const float*)d_in[3];
    const float* b0_1  = (const float*)d_in[4];
    const float* w0_2  = (const float*)d_in[5];
    const float* b0_2  = (const float*)d_in[6];
    const float* w0_3  = (const float*)d_in[7];
    const float* b0_3  = (const float*)d_in[8];
    const float* w0_4  = (const float*)d_in[9];
    const float* b0_4  = (const float*)d_in[10];
    const float* w1    = (const float*)d_in[11];
    const float* b1    = (const float*)d_in[12];
    const float* w2    = (const float*)d_in[13];
    const float* b2    = (const float*)d_in[14];
    const float* fc1w  = (const float*)d_in[15];
    const float* fc2w  = (const float*)d_in[16];
    const float* fc2b  = (const float*)d_in[17];
    const float* compat= (const float*)d_in[18];
    const float* sw    = (const float*)d_in[19];
    float* out = (float*)d_out;

    cudaFuncSetAttribute(k_conv, cudaFuncAttributeMaxDynamicSharedMemorySize, SMEM_TOTAL);

    k_zero_halo<<<1384, 256>>>();
    k_wt<<<256, 256>>>(w0_0);
    k_tr<<<dim3(2, 56, 128), dim3(32, 8)>>>(x);
    k_conv<<<N_CTAS, 256, SMEM_TOTAL>>>(b0_0);
    k_cent<<<256, 256>>>(w0_1, w0_2, w0_3, w0_4, fc1w, w1, w2);
    k_tail<<<16, 256>>>(b0_1, b0_2, b0_3, b0_4, b1, b2, fc2w, fc2b, compat, sw, out);
}